// round 14
// baseline (speedup 1.0000x reference)
#include <cuda_runtime.h>
#include <cuda_fp16.h>
#include <math.h>
#include <stdint.h>

// Problem constants
#define BB    64
#define LL    512
#define DDIM  512
#define HH    8
#define EE    64
#define DFF   2048
#define NMODES 32
#define NAPP  10000
#define KCAT  536    // D + 24
#define MTOT  (BB*LL)
#define MMODE (BB*64)   // 4096 mode-rows (32 re + 32 im per batch)
#define NPADP 10112  // proj N padded (mult of 64)
#define KPADP 576    // proj K padded (mult of 32)
#define TWOPI 6.283185307179586476925286766559

// ---------------------------------------------------------------------------
// Scratch (device globals — no runtime allocation allowed)
// ---------------------------------------------------------------------------
__device__ __align__(128) float g_acc[8*BB*DDIM];    // 8 partial sums per (b,d)

// fp16 activation planes
__device__ __align__(128) __half g_pa [MTOT*DDIM];
__device__ __align__(128) __half g_pb [MTOT*DDIM];
__device__ __align__(128) __half g_px [MTOT*DDIM];   // residual x [b,l,d]
__device__ __align__(128) __half g_pxt[MTOT*DDIM];   // x transposed [b,d,l]
__device__ __align__(128) __half g_yp [MTOT*DFF];
// fp16 weights / twiddles
__device__ __align__(128) __half g_wq [2*DDIM*DDIM];
__device__ __align__(128) __half g_wo [2*DDIM*DDIM];
__device__ __align__(128) __half g_c1 [2*DFF*DDIM];
__device__ __align__(128) __half g_c2 [2*DDIM*DFF];
__device__ __align__(128) __half g_tw [64*512];      // fwd DFT (32 re + 32 im rows)
__device__ __align__(128) __half g_itw[512*64];      // inv DFT
__device__ __align__(128) __half g_cath[128*KPADP];  // padded cat (fp16)
__device__ __align__(128) __half g_pwh[NPADP*KPADP]; // padded proj weights (fp16)

// ---------------------------------------------------------------------------
// PTX helpers
// ---------------------------------------------------------------------------
__device__ __forceinline__ uint32_t smem_u32(const void* p) {
    uint32_t a;
    asm("{ .reg .u64 t; cvta.to.shared.u64 t, %1; cvt.u32.u64 %0, t; }" : "=r"(a) : "l"(p));
    return a;
}
#define CP16(d, s)  asm volatile("cp.async.cg.shared.global [%0], [%1], 16;" :: "r"(d), "l"(s) : "memory")
#define CP_COMMIT() asm volatile("cp.async.commit_group;" ::: "memory")
#define CP_WAIT2()  asm volatile("cp.async.wait_group 2;" ::: "memory")
#define CP_WAIT0()  asm volatile("cp.async.wait_group 0;" ::: "memory")

#define LDSM4(r0, r1, r2, r3, a) \
    asm volatile("ldmatrix.sync.aligned.m8n8.x4.shared.b16 {%0,%1,%2,%3}, [%4];" \
        : "=r"(r0), "=r"(r1), "=r"(r2), "=r"(r3) : "r"(a))

#define MMAF16(c, a0, a1, a2, a3, b0, b1) \
    asm volatile("mma.sync.aligned.m16n8k16.row.col.f32.f16.f16.f32 " \
        "{%0,%1,%2,%3}, {%4,%5,%6,%7}, {%8,%9}, {%0,%1,%2,%3};" \
        : "+f"((c)[0]), "+f"((c)[1]), "+f"((c)[2]), "+f"((c)[3]) \
        : "r"(a0), "r"(a1), "r"(a2), "r"(a3), "r"(b0), "r"(b1))

// ---------------------------------------------------------------------------
// Tensor-core GEMM (fp16 x fp16 -> fp32 accum): C[m,n] = sum_k A[m,k]*B[n,k]
//   CTA tile 128x64, 256 threads (8 warps, 4m x 2n), warp tile 32x32.
//   BK=32, 80B pitch, 4-stage cp.async, 3 CTAs/SM.
// ---------------------------------------------------------------------------
#define MG_PIT  80
#define MG_PLA  (128 * MG_PIT)
#define MG_PLB  (64 * MG_PIT)
#define MG_STG  (MG_PLA + MG_PLB)    // 15360 B
#define MG_NSTG 4
#define MG_SMEM (MG_NSTG * MG_STG)   // 61440 B
#define OA 0
#define OB MG_PLA

template <int RELU, int ADDC, int BIAS, int OUTPL>
__global__ void __launch_bounds__(256, 3)
mgemm_k(const __half* __restrict__ A, const __half* __restrict__ B,
        const float* __restrict__ bias, const __half* __restrict__ Cin,
        float* __restrict__ C, __half* __restrict__ Oh, int K, int Nout, int Mout) {
    extern __shared__ __align__(128) char smem[];
    const uint32_t sb = smem_u32(smem);
    const int tid = threadIdx.x, lane = tid & 31, wid = tid >> 5;
    const int wm = wid & 3, wn = wid >> 2;       // warps 4 x 2, 32x32 each
    const int m0 = blockIdx.y * 128, n0 = blockIdx.x * 64;

    float acc[2][4][4];
#pragma unroll
    for (int i = 0; i < 2; i++)
#pragma unroll
        for (int j = 0; j < 4; j++)
#pragma unroll
            for (int t = 0; t < 4; t++) acc[i][j][t] = 0.f;

    const uint32_t a_off = (uint32_t)((wm * 32 + (lane & 7) + ((lane >> 3) & 1) * 8) * MG_PIT
                                      + (lane >> 4) * 16);
    const uint32_t b_off = (uint32_t)((wn * 32 + ((lane >> 4) & 1) * 8 + (lane & 7)) * MG_PIT
                                      + ((lane >> 3) & 1) * 16);

    auto cpAB = [&](int c, int s) {
        const uint32_t base = sb + s * MG_STG;
        const size_t ko = (size_t)c * 32;
        {
            const int r = tid >> 1, h = tid & 1;
            const __half* a0 = A + (size_t)(m0 + r) * K + ko + h * 16;
            const uint32_t doff = base + OA + (uint32_t)(r * MG_PIT + h * 32);
            CP16(doff, a0); CP16(doff + 16, a0 + 8);
        }
        {
            const int r = tid >> 2, q = tid & 3;
            const __half* b0 = B + (size_t)(n0 + r) * K + ko + q * 8;
            CP16(base + OB + (uint32_t)(r * MG_PIT + q * 16), b0);
        }
        CP_COMMIT();
    };

    const int NC = K >> 5;
#pragma unroll
    for (int i = 0; i < 3; i++) {
        if (i < NC) cpAB(i, i);
        else        CP_COMMIT();
    }
    for (int c = 0; c < NC; c++) {
        const int s = c & (MG_NSTG - 1);
        CP_WAIT2();
        __syncthreads();
        if (c + 3 < NC) cpAB(c + 3, (c + 3) & (MG_NSTG - 1));
        else            CP_COMMIT();
        const uint32_t base = sb + s * MG_STG;
#pragma unroll
        for (int ks = 0; ks < 2; ks++) {
            const uint32_t koff = ks * 32;
            uint32_t a[2][4];
#pragma unroll
            for (int mi = 0; mi < 2; mi++)
                LDSM4(a[mi][0], a[mi][1], a[mi][2], a[mi][3],
                      base + OA + a_off + mi * (16 * MG_PIT) + koff);
#pragma unroll
            for (int np = 0; np < 2; np++) {
                uint32_t b[4];
                LDSM4(b[0], b[1], b[2], b[3],
                      base + OB + b_off + np * (16 * MG_PIT) + koff);
#pragma unroll
                for (int mi = 0; mi < 2; mi++) {
#pragma unroll
                    for (int t = 0; t < 2; t++) {
                        MMAF16(acc[mi][np * 2 + t], a[mi][0], a[mi][1], a[mi][2], a[mi][3],
                               b[2*t], b[2*t + 1]);
                    }
                }
            }
        }
    }
    CP_WAIT0();

    // epilogue
#pragma unroll
    for (int mi = 0; mi < 2; mi++) {
        const int r0 = m0 + wm * 32 + mi * 16 + (lane >> 2);
#pragma unroll
        for (int ni = 0; ni < 4; ni++) {
            const int col = n0 + wn * 32 + ni * 8 + 2 * (lane & 3);
            if (col >= Nout) continue;
            float v00 = acc[mi][ni][0], v01 = acc[mi][ni][1];
            float v10 = acc[mi][ni][2], v11 = acc[mi][ni][3];
            if (BIAS) {
                float2 bv = *(const float2*)&bias[col];
                v00 += bv.x; v01 += bv.y; v10 += bv.x; v11 += bv.y;
            }
            const size_t o0 = (size_t)r0 * Nout + col;
            const size_t o1 = (size_t)(r0 + 8) * Nout + col;
            const bool m0ok = (r0 < Mout), m1ok = (r0 + 8 < Mout);
            if (ADDC) {
                if (m0ok) {
                    __half2 c0 = *(const __half2*)&Cin[o0];
                    v00 += __half2float(c0.x); v01 += __half2float(c0.y);
                }
                if (m1ok) {
                    __half2 c1 = *(const __half2*)&Cin[o1];
                    v10 += __half2float(c1.x); v11 += __half2float(c1.y);
                }
            }
            if (RELU) {
                v00 = fmaxf(v00, 0.f); v01 = fmaxf(v01, 0.f);
                v10 = fmaxf(v10, 0.f); v11 = fmaxf(v11, 0.f);
            }
            if (OUTPL) {
                __half2 h0, h1;
                h0.x = __float2half_rn(v00); h0.y = __float2half_rn(v01);
                h1.x = __float2half_rn(v10); h1.y = __float2half_rn(v11);
                if (m0ok) *(__half2*)&Oh[o0] = h0;
                if (m1ok) *(__half2*)&Oh[o1] = h1;
            } else {
                if (m0ok) *(float2*)&C[o0] = make_float2(v00, v01);
                if (m1ok) *(float2*)&C[o1] = make_float2(v10, v11);
            }
        }
    }
}

template <int R, int AD, int BI, int OP>
static void mg2(const __half* A, const __half* B, const float* bias,
                const __half* Cin, float* C, __half* Oh,
                int M, int Npad, int K, int Nout, int Mout) {
    cudaFuncSetAttribute(mgemm_k<R, AD, BI, OP>,
                         cudaFuncAttributeMaxDynamicSharedMemorySize, MG_SMEM);
    dim3 g(Npad / 64, (M + 127) / 128);
    mgemm_k<R, AD, BI, OP><<<g, 256, MG_SMEM>>>(A, B, bias, Cin, C, Oh, K, Nout, Mout);
}

// ---------------------------------------------------------------------------
// Merged weight conversion (wq, wo, c1, c2, padded proj) — one launch
// ---------------------------------------------------------------------------
#define NW1 (2*DDIM*DDIM)   // 524288
#define NW2 (2*DFF*DDIM)    // 2097152
#define NWP (NPADP*KPADP)   // 5824512
#define NW_TOTAL (2*NW1 + 2*NW2 + NWP)

__global__ void cvt_all_k(const float* __restrict__ Wq, const float* __restrict__ Wo,
                          const float* __restrict__ C1, const float* __restrict__ C2,
                          const float* __restrict__ PW,
                          __half* __restrict__ wq, __half* __restrict__ wo,
                          __half* __restrict__ c1, __half* __restrict__ c2,
                          __half* __restrict__ pwh) {
    int i = blockIdx.x * blockDim.x + threadIdx.x;
    if (i < NW1) { wq[i] = __float2half_rn(Wq[i]); return; }
    i -= NW1;
    if (i < NW1) { wo[i] = __float2half_rn(Wo[i]); return; }
    i -= NW1;
    if (i < NW2) { c1[i] = __float2half_rn(C1[i]); return; }
    i -= NW2;
    if (i < NW2) { c2[i] = __float2half_rn(C2[i]); return; }
    i -= NW2;
    if (i < NWP) {
        int r = i / KPADP, c = i - r * KPADP;
        pwh[i] = (r < NAPP && c < KCAT) ? __float2half_rn(PW[(size_t)r * KCAT + c]) : __half(0.f);
    }
}

__global__ void init_tw_k(__half* tw, __half* itw) {
    int i = blockIdx.x * blockDim.x + threadIdx.x;   // 0..32767
    {
        int c = i >> 9, l = i & 511;
        double v;
        if (c < 32)  v = cos((TWOPI / 512.0) * (double)(l * c));
        else         v = -sin((TWOPI / 512.0) * (double)(l * (c - 32)));
        tw[i] = __float2half_rn((float)v);
    }
    {
        int l = i >> 6, c = i & 63;
        double v;
        if (c == 0)       v = 1.0 / 512.0;
        else if (c < 32)  v = 2.0 * cos((TWOPI / 512.0) * (double)(l * c)) / 512.0;
        else if (c == 32) v = 0.0;
        else              v = -2.0 * sin((TWOPI / 512.0) * (double)(l * (c - 32))) / 512.0;
        itw[i] = __float2half_rn((float)v);
    }
}

// ---------------------------------------------------------------------------
// Embedding -> fp16 plane
// ---------------------------------------------------------------------------
__global__ void embed_k(const int* __restrict__ x_app, const float* __restrict__ x_time,
                        const float* __restrict__ emb, const float* __restrict__ tw,
                        const float* __restrict__ tb, __half* __restrict__ px) {
    int b = blockIdx.y, l = blockIdx.x;
    int d = threadIdx.x * 2;
    int a = x_app[b * LL + l];
    float t = x_time[b * LL + l];
    size_t idx = ((size_t)b * LL + l) * DDIM + d;
    float2 e = *(const float2*)&emb[(size_t)a * DDIM + d];
    float2 w = *(const float2*)&tw[d];
    float2 bb = *(const float2*)&tb[d];
    __half2 h;
    h.x = __float2half_rn(e.x + t * w.x + bb.x);
    h.y = __float2half_rn(e.y + t * w.y + bb.y);
    *(__half2*)&px[idx] = h;
}

// ---------------------------------------------------------------------------
// Per-batch 512x512 transpose, fp16 -> fp16 (layer-0 entry only)
// ---------------------------------------------------------------------------
__global__ void transpose_half_k(const __half* __restrict__ in, __half* __restrict__ out) {
    __shared__ __half tile[32][33];
    int b = blockIdx.z;
    const __half* ip = in + (size_t)b * (512 * 512);
    __half* op = out + (size_t)b * (512 * 512);
    int i0 = blockIdx.y * 32, j0 = blockIdx.x * 32;
#pragma unroll
    for (int r = 0; r < 32; r += 8)
        tile[threadIdx.y + r][threadIdx.x] =
            ip[(size_t)(i0 + threadIdx.y + r) * 512 + j0 + threadIdx.x];
    __syncthreads();
#pragma unroll
    for (int r = 0; r < 32; r += 8)
        op[(size_t)(j0 + threadIdx.y + r) * 512 + i0 + threadIdx.x] =
            tile[threadIdx.x][threadIdx.y + r];
}

// ---------------------------------------------------------------------------
// Mode transposes (per batch): [(b,d)512, m64] <-> [(b,m)64, d512]
// ---------------------------------------------------------------------------
__global__ void mtrans_fwd_k(const __half* __restrict__ in, __half* __restrict__ out) {
    __shared__ __half tile[32][33];
    int b = blockIdx.z;
    int m0 = blockIdx.x * 32, d0 = blockIdx.y * 32;
    const __half* ip = in + (size_t)b * 512 * 64;
    __half* op = out + (size_t)b * 64 * 512;
#pragma unroll
    for (int r = 0; r < 32; r += 8)
        tile[threadIdx.y + r][threadIdx.x] =
            ip[(size_t)(d0 + threadIdx.y + r) * 64 + m0 + threadIdx.x];
    __syncthreads();
#pragma unroll
    for (int r = 0; r < 32; r += 8)
        op[(size_t)(m0 + threadIdx.y + r) * 512 + d0 + threadIdx.x] =
            tile[threadIdx.x][threadIdx.y + r];
}

__global__ void mtrans_bwd_k(const __half* __restrict__ in, const float* __restrict__ bo,
                             __half* __restrict__ out) {
    __shared__ __half tile[32][33];
    int b = blockIdx.z;
    int d0 = blockIdx.x * 32, m0 = blockIdx.y * 32;
    const __half* ip = in + (size_t)b * 64 * 512;
    __half* op = out + (size_t)b * 512 * 64;
#pragma unroll
    for (int r = 0; r < 32; r += 8) {
        int m = m0 + threadIdx.y + r;
        float v = __half2float(ip[(size_t)m * 512 + d0 + threadIdx.x]);
        if (m == 0) v += 512.f * bo[d0 + threadIdx.x];
        tile[threadIdx.y + r][threadIdx.x] = __float2half_rn(v);
    }
    __syncthreads();
#pragma unroll
    for (int r = 0; r < 32; r += 8)
        op[(size_t)(d0 + threadIdx.y + r) * 64 + m0 + threadIdx.x] =
            tile[threadIdx.x][threadIdx.y + r];
}

// ---------------------------------------------------------------------------
// Complex mode mixing in [(b,m),d] layout (fp16 I/O); folds +512*bq at mode 0
// ---------------------------------------------------------------------------
__global__ void modemix_k(const __half* __restrict__ qft, const float* __restrict__ bq,
                          const float* __restrict__ wr, const float* __restrict__ wi,
                          __half* __restrict__ g) {
    int mode = blockIdx.x, h = blockIdx.y;
    __shared__ float Xr[64][32], Xi[64][32], Wr[32][64], Wi[32][64];
    int tid = threadIdx.x;
    int tb = tid >> 4, to = tid & 15;
    float cr[4][4], ci[4][4];
#pragma unroll
    for (int a = 0; a < 4; a++)
#pragma unroll
        for (int c = 0; c < 4; c++) { cr[a][c] = 0.f; ci[a][c] = 0.f; }
    for (int i0 = 0; i0 < 64; i0 += 32) {
#pragma unroll
        for (int j = 0; j < 8; j++) {
            int e = tid * 8 + j;
            int b = e >> 5, ii = e & 31;
            int dd = h * 64 + i0 + ii;
            float vr = __half2float(qft[((size_t)b * 64 + mode) * 512 + dd]);
            if (mode == 0) vr += 512.f * bq[dd];
            Xr[b][ii] = vr;
            Xi[b][ii] = __half2float(qft[((size_t)b * 64 + 32 + mode) * 512 + dd]);
            int wi2 = e >> 6, o = e & 63;
            size_t widx = (((size_t)h * 64 + i0 + wi2) * 64 + o) * 32 + mode;
            Wr[wi2][o] = wr[widx];
            Wi[wi2][o] = wi[widx];
        }
        __syncthreads();
#pragma unroll 8
        for (int ii = 0; ii < 32; ii++) {
            float xr[4], xi4[4], wrv[4], wiv[4];
#pragma unroll
            for (int a = 0; a < 4; a++) { xr[a] = Xr[tb*4+a][ii]; xi4[a] = Xi[tb*4+a][ii]; }
#pragma unroll
            for (int c = 0; c < 4; c++) { wrv[c] = Wr[ii][to*4+c]; wiv[c] = Wi[ii][to*4+c]; }
#pragma unroll
            for (int a = 0; a < 4; a++)
#pragma unroll
                for (int c = 0; c < 4; c++) {
                    cr[a][c] += xr[a] * wrv[c] - xi4[a] * wiv[c];
                    ci[a][c] += xr[a] * wiv[c] + xi4[a] * wrv[c];
                }
        }
        __syncthreads();
    }
#pragma unroll
    for (int a = 0; a < 4; a++) {
        int b = tb * 4 + a;
#pragma unroll
        for (int c = 0; c < 4; c++) {
            int o = to * 4 + c;
            int dd = h * 64 + o;
            g[((size_t)b * 64 + mode) * 512 + dd] = __float2half_rn(cr[a][c]);
            g[((size_t)b * 64 + 32 + mode) * 512 + dd] = __float2half_rn(ci[a][c]);
        }
    }
}

// ---------------------------------------------------------------------------
// Fused transpose+decomp: input tmpT [(b,d),l]  -> out [b,l,d]
//   grid (16 dtiles, 8 ltiles, BB), block 256.
//   smem tile [32 d][88 l window], pitch 98 halfs (conflict-free: 49 banks).
// ---------------------------------------------------------------------------
__global__ void decompT_k(const __half* __restrict__ in, __half* __restrict__ out) {
    __shared__ __half t[32 * 98];
    const int b = blockIdx.z;
    const int d0 = blockIdx.x * 32;
    const int l0 = blockIdx.y * 64;
    const int tid = threadIdx.x;
    {
        const int row = tid >> 3, tx = tid & 7;   // 32 rows x 8 loaders
        const __half* src = in + ((size_t)b * 512 + d0 + row) * 512;
#pragma unroll
        for (int j = 0; j < 11; j++) {
            int col = tx * 11 + j;                // 0..87
            int g = l0 - 12 + col;
            g = g < 0 ? 0 : (g > 511 ? 511 : g);
            t[row * 98 + col] = src[g];
        }
    }
    __syncthreads();
    const int d = tid & 31, lc = tid >> 5;        // lc 0..7
    const __half* tr = t + d * 98 + lc * 8;
    float sum = 0.f;
#pragma unroll
    for (int j = 0; j < 25; j++) sum += __half2float(tr[j]);
    size_t ob = ((size_t)b * 512 + l0 + lc * 8) * 512 + d0 + d;
#pragma unroll
    for (int i = 0; i < 8; i++) {
        float v = __half2float(tr[12 + i]) - sum * (1.f / 25.f);
        out[ob + (size_t)i * 512] = __float2half_rn(v);
        if (i < 7) sum += __half2float(tr[25 + i]) - __half2float(tr[i]);
    }
}

// ---------------------------------------------------------------------------
// Dual-output decomp: input [b,l,d] -> px [b,l,d] AND pxt [(b,d),l]
//   grid (16 dtiles, 8 ltiles, BB), block 256.
// ---------------------------------------------------------------------------
__global__ void decomp2dual_k(const __half* __restrict__ in, __half* __restrict__ px,
                              __half* __restrict__ pxt) {
    __shared__ __half t[88 * 34];    // [l window][d], pitch 34 (17 banks)
    __shared__ __half o[32 * 66];    // [d][l] out tile, pitch 66 (33 banks)
    const int b = blockIdx.z;
    const int d0 = blockIdx.x * 32;
    const int l0 = blockIdx.y * 64;
    const int tid = threadIdx.x;
    {
        const int d = tid & 31, r0 = tid >> 5;
        for (int r = r0; r < 88; r += 8) {
            int g = l0 - 12 + r;
            g = g < 0 ? 0 : (g > 511 ? 511 : g);
            t[r * 34 + d] = in[((size_t)b * 512 + g) * 512 + d0 + d];
        }
    }
    __syncthreads();
    const int d = tid & 31, lc = tid >> 5;
    float sum = 0.f;
#pragma unroll
    for (int j = 0; j < 25; j++) sum += __half2float(t[(lc * 8 + j) * 34 + d]);
    size_t pb_ = ((size_t)b * 512 + l0 + lc * 8) * 512 + d0 + d;
#pragma unroll
    for (int i = 0; i < 8; i++) {
        float v = __half2float(t[(lc * 8 + 12 + i) * 34 + d]) - sum * (1.f / 25.f);
        __half hv = __float2half_rn(v);
        px[pb_ + (size_t)i * 512] = hv;
        o[d * 66 + lc * 8 + i] = hv;
        if (i < 7)
            sum += __half2float(t[(lc * 8 + 25 + i) * 34 + d])
                 - __half2float(t[(lc * 8 + i) * 34 + d]);
    }
    __syncthreads();
    {
        const int row = tid >> 3, tx = tid & 7;   // 32 rows x 8 writers
        __half* dst = pxt + ((size_t)b * 512 + d0 + row) * 512 + l0 + tx * 8;
        const __half* srw = o + row * 66 + tx * 8;
#pragma unroll
        for (int j = 0; j < 4; j++)
            *(uint32_t*)&dst[j * 2] = *(const uint32_t*)&srw[j * 2];
    }
}

// ---------------------------------------------------------------------------
// LayerNorm (fp16) + parallel last-token concat
// ---------------------------------------------------------------------------
__device__ __forceinline__ float blocksum512(float v, float* red) {
    int lane = threadIdx.x & 31, w = threadIdx.x >> 5;
#pragma unroll
    for (int o = 16; o; o >>= 1) v += __shfl_down_sync(0xffffffffu, v, o);
    if (lane == 0) red[w] = v;
    __syncthreads();
    if (w == 0) {
        float t = (lane < 16) ? red[lane] : 0.f;
#pragma unroll
        for (int o = 8; o; o >>= 1) t += __shfl_down_sync(0xffffffffu, t, o);
        if (lane == 0) red[0] = t;
    }
    __syncthreads();
    float r = red[0];
    __syncthreads();
    return r;
}

__global__ void layernorm_k(const __half* __restrict__ x, const float* __restrict__ w,
                            const float* __restrict__ bb, __half* __restrict__ xh) {
    __shared__ float red[32];
    int b = blockIdx.y, l = blockIdx.x, d = threadIdx.x;
    size_t base = ((size_t)b * LL + l) * DDIM;
    float v = __half2float(x[base + d]);
    float mu = blocksum512(v, red) * (1.f / 512.f);
    float dv = v - mu;
    float var = blocksum512(dv * dv, red) * (1.f / 512.f);
    xh[base + d] = __float2half_rn(dv * rsqrtf(var + 1e-5f) * w[d] + bb[d]);
}

__global__ void partial_sum_k(const __half* __restrict__ xh, float* __restrict__ acc) {
    int b = blockIdx.y, d = threadIdx.x, part = blockIdx.x;
    int l0 = part * 64;
    float s = 0.f;
    for (int l = l0; l < l0 + 64; l++)
        s += __half2float(xh[((size_t)b * LL + l) * DDIM + d]);
    acc[((size_t)part * BB + b) * DDIM + d] = s;
}

__global__ void lastcat_k(const __half* __restrict__ xh, const float* __restrict__ acc,
                          const float* __restrict__ time_vecs, __half* __restrict__ cath) {
    int b = blockIdx.x, d = threadIdx.x;
    float s = 0.f;
#pragma unroll
    for (int p = 0; p < 8; p++) s += acc[((size_t)p * BB + b) * DDIM + d];
    float v = __half2float(xh[((size_t)b * LL + 511) * DDIM + d]) - s * (1.f / 512.f);
    cath[b * KPADP + d] = __float2half_rn(v);
    if (d < 24)
        cath[b * KPADP + 512 + d] = __float2half_rn(time_vecs[((size_t)b * LL + 511) * 24 + d]);
}

__global__ void zero_cath_k(__half* __restrict__ cath) {
    int i = blockIdx.x * blockDim.x + threadIdx.x;
    if (i < 128 * KPADP) cath[i] = __half(0.f);
}

// ---------------------------------------------------------------------------
// Host orchestration
// ---------------------------------------------------------------------------
extern "C" void kernel_launch(void* const* d_in, const int* in_sizes, int n_in,
                              void* d_out, int out_size) {
    (void)in_sizes; (void)n_in; (void)out_size;
    const int*   x_app     = (const int*)  d_in[0];
    const float* x_time    = (const float*)d_in[1];
    const float* time_vecs = (const float*)d_in[2];
    const float* emb       = (const float*)d_in[4];
    const float* time_w    = (const float*)d_in[5];
    const float* time_b    = (const float*)d_in[6];
    const float* Wq        = (const float*)d_in[7];
    const float* bq        = (const float*)d_in[8];
    const float* Wo        = (const float*)d_in[9];
    const float* bo        = (const float*)d_in[10];
    const float* four_wr   = (const float*)d_in[11];
    const float* four_wi   = (const float*)d_in[12];
    const float* conv1     = (const float*)d_in[13];
    const float* conv2     = (const float*)d_in[14];
    const float* norm_w    = (const float*)d_in[15];
    const float* norm_b    = (const float*)d_in[16];
    const float* proj_w    = (const float*)d_in[17];
    const float* proj_b    = (const float*)d_in[18];

    float *gacc;
    __half *pa, *pb, *px, *pxt, *yp, *wq, *wo, *c1, *c2, *tw, *itw, *cath, *pwh;
    cudaGetSymbolAddress((void**)&gacc, g_acc);
    cudaGetSymbolAddress((void**)&pa,   g_pa);
    cudaGetSymbolAddress((void**)&pb,   g_pb);
    cudaGetSymbolAddress((void**)&px,   g_px);
    cudaGetSymbolAddress((void**)&pxt,  g_pxt);
    cudaGetSymbolAddress((void**)&yp,   g_yp);
    cudaGetSymbolAddress((void**)&wq,   g_wq);
    cudaGetSymbolAddress((void**)&wo,   g_wo);
    cudaGetSymbolAddress((void**)&c1,   g_c1);
    cudaGetSymbolAddress((void**)&c2,   g_c2);
    cudaGetSymbolAddress((void**)&tw,   g_tw);
    cudaGetSymbolAddress((void**)&itw,  g_itw);
    cudaGetSymbolAddress((void**)&cath, g_cath);
    cudaGetSymbolAddress((void**)&pwh,  g_pwh);

    const int M = MTOT;   // 32768

    init_tw_k<<<128, 256>>>(tw, itw);
    cvt_all_k<<<(NW_TOTAL + 255) / 256, 256>>>(Wq, Wo, conv1, conv2, proj_w,
                                               wq, wo, c1, c2, pwh);
    embed_k<<<dim3(LL, BB), 256>>>(x_app, x_time, emb, time_w, time_b, px);

    dim3 tgrid(16, 16, BB), tblk(32, 8);
    dim3 mfgrid(2, 16, BB);   // mtrans_fwd
    dim3 mbgrid(16, 2, BB);   // mtrans_bwd
    dim3 dgrid(16, 8, BB);    // decompT / decomp2dual

    // layer-0 entry: pxt = transpose(px)
    transpose_half_k<<<tgrid, tblk>>>(px, pxt);

    for (int l = 0; l < 2; l++) {
        const float* bql = bq + (size_t)l * DDIM;
        const float* bol = bo + (size_t)l * DDIM;
        const float* wrl = four_wr + (size_t)l * HH * EE * EE * NMODES;
        const float* wil = four_wi + (size_t)l * HH * EE * EE * NMODES;
        size_t owq = (size_t)l * DDIM * DDIM;
        size_t oc1 = (size_t)l * DFF * DDIM;
        size_t oc2 = (size_t)l * DDIM * DFF;

        // fwd DFT: Xft[(b,d),m] = xT @ TW^T
        mg2<0,0,0,1>(pxt, tw, nullptr, nullptr, nullptr, pa, M, 64, 512, 64, M);
        // Xft -> [(b,m),d]
        mtrans_fwd_k<<<mfgrid, tblk>>>(pa, pb);
        // q_ft = Xft @ Wq^T  (mode space: M=4096)
        mg2<0,0,0,1>(pb, wq + owq, nullptr, nullptr, nullptr, pa, MMODE, 512, 512, 512, MMODE);
        // complex mode mixing (+512*bq at DC)
        modemix_k<<<dim3(NMODES, HH), 256>>>(pa, bql, wrl, wil, pb);
        // G' = G @ Wo^T  (mode space)
        mg2<0,0,0,1>(pb, wo + owq, nullptr, nullptr, nullptr, pa, MMODE, 512, 512, 512, MMODE);
        // G' -> [(b,d),m], +512*bo at DC
        mtrans_bwd_k<<<mbgrid, tblk>>>(pa, bol, pb);
        // inv DFT + residual: tmpT[(b,d),l] = G'T @ ITW^T + xT   (K=64)
        mg2<0,1,0,1>(pb, itw, nullptr, pxt, nullptr, pa, M, 512, 64, 512, M);
        // fused transpose+decomp: tmpT -> x [b,l,d]
        decompT_k<<<dgrid, 256>>>(pa, px);
        // y = relu(x @ c1^T)
        mg2<1,0,0,1>(px, c1 + oc1, nullptr, nullptr, nullptr, yp, M, 2048, 512, 2048, M);
        // tmp = y @ c2^T + x
        mg2<0,1,0,1>(yp, c2 + oc2, nullptr, px, nullptr, pb, M, 512, 2048, 512, M);
        // x = tmp - movavg(tmp)  (dual: px + pxt for next layer)
        decomp2dual_k<<<dgrid, 256>>>(pb, px, pxt);
    }

    layernorm_k<<<dim3(LL, BB), DDIM>>>(px, norm_w, norm_b, pb);
    zero_cath_k<<<(128*KPADP + 255)/256, 256>>>(cath);
    partial_sum_k<<<dim3(8, BB), DDIM>>>(pb, gacc);
    lastcat_k<<<BB, DDIM>>>(pb, gacc, time_vecs, cath);
    // score = cat @ proj_w^T + proj_b  (f32 out, Mout=64)
    mg2<0,0,1,0>(cath, pwh, proj_b, nullptr, (float*)d_out, nullptr,
                 128, NPADP, KPADP, NAPP, BB);
}

// round 15
// speedup vs baseline: 1.0219x; 1.0219x over previous
#include <cuda_runtime.h>
#include <cuda_fp16.h>
#include <math.h>
#include <stdint.h>

// Problem constants
#define BB    64
#define LL    512
#define DDIM  512
#define HH    8
#define EE    64
#define DFF   2048
#define NMODES 32
#define NAPP  10000
#define KCAT  536    // D + 24
#define MTOT  (BB*LL)
#define MMODE (BB*64)   // 4096 mode-rows (32 re + 32 im per batch)
#define NPADP 10112  // proj N padded (mult of 64)
#define KPADP 576    // proj K padded (mult of 32)
#define TWOPI 6.283185307179586476925286766559

// ---------------------------------------------------------------------------
// Scratch (device globals — no runtime allocation allowed)
// ---------------------------------------------------------------------------
__device__ __align__(128) float g_acc[8*BB*DDIM];    // 8 partial sums per (b,d)
__device__ __align__(128) float2 g_st[MTOT];         // layernorm stats (mu, rs)

// fp16 activation planes
__device__ __align__(128) __half g_pa [MTOT*DDIM];
__device__ __align__(128) __half g_pb [MTOT*DDIM];
__device__ __align__(128) __half g_px [MTOT*DDIM];   // residual x [b,l,d]
__device__ __align__(128) __half g_pxt[MTOT*DDIM];   // x transposed [b,d,l]
__device__ __align__(128) __half g_yp [MTOT*DFF];
// fp16 weights / twiddles
__device__ __align__(128) __half g_wq [2*DDIM*DDIM];
__device__ __align__(128) __half g_wo [2*DDIM*DDIM];
__device__ __align__(128) __half g_c1 [2*DFF*DDIM];
__device__ __align__(128) __half g_c2 [2*DDIM*DFF];
__device__ __align__(128) __half g_tw [64*512];      // fwd DFT (32 re + 32 im rows)
__device__ __align__(128) __half g_itw[512*64];      // inv DFT
__device__ __align__(128) __half g_cath[128*KPADP];  // padded cat (fp16)
__device__ __align__(128) __half g_pwh[NPADP*KPADP]; // padded proj weights (fp16)

// ---------------------------------------------------------------------------
// PTX helpers
// ---------------------------------------------------------------------------
__device__ __forceinline__ uint32_t smem_u32(const void* p) {
    uint32_t a;
    asm("{ .reg .u64 t; cvta.to.shared.u64 t, %1; cvt.u32.u64 %0, t; }" : "=r"(a) : "l"(p));
    return a;
}
#define CP16(d, s)  asm volatile("cp.async.cg.shared.global [%0], [%1], 16;" :: "r"(d), "l"(s) : "memory")
#define CP_COMMIT() asm volatile("cp.async.commit_group;" ::: "memory")
#define CP_WAIT2()  asm volatile("cp.async.wait_group 2;" ::: "memory")
#define CP_WAIT0()  asm volatile("cp.async.wait_group 0;" ::: "memory")

#define LDSM4(r0, r1, r2, r3, a) \
    asm volatile("ldmatrix.sync.aligned.m8n8.x4.shared.b16 {%0,%1,%2,%3}, [%4];" \
        : "=r"(r0), "=r"(r1), "=r"(r2), "=r"(r3) : "r"(a))

#define MMAF16(c, a0, a1, a2, a3, b0, b1) \
    asm volatile("mma.sync.aligned.m16n8k16.row.col.f32.f16.f16.f32 " \
        "{%0,%1,%2,%3}, {%4,%5,%6,%7}, {%8,%9}, {%0,%1,%2,%3};" \
        : "+f"((c)[0]), "+f"((c)[1]), "+f"((c)[2]), "+f"((c)[3]) \
        : "r"(a0), "r"(a1), "r"(a2), "r"(a3), "r"(b0), "r"(b1))

// ---------------------------------------------------------------------------
// Tensor-core GEMM (fp16 x fp16 -> fp32 accum): C[m,n] = sum_k A[m,k]*B[n,k]
//   CTA tile 128x64, 256 threads (8 warps, 4m x 2n), warp tile 32x32.
//   BK=32, 80B pitch, 4-stage cp.async, 3 CTAs/SM.
// ---------------------------------------------------------------------------
#define MG_PIT  80
#define MG_PLA  (128 * MG_PIT)
#define MG_PLB  (64 * MG_PIT)
#define MG_STG  (MG_PLA + MG_PLB)    // 15360 B
#define MG_NSTG 4
#define MG_SMEM (MG_NSTG * MG_STG)   // 61440 B
#define OA 0
#define OB MG_PLA

template <int RELU, int ADDC, int BIAS, int OUTPL>
__global__ void __launch_bounds__(256, 3)
mgemm_k(const __half* __restrict__ A, const __half* __restrict__ B,
        const float* __restrict__ bias, const __half* __restrict__ Cin,
        float* __restrict__ C, __half* __restrict__ Oh, int K, int Nout, int Mout) {
    extern __shared__ __align__(128) char smem[];
    const uint32_t sb = smem_u32(smem);
    const int tid = threadIdx.x, lane = tid & 31, wid = tid >> 5;
    const int wm = wid & 3, wn = wid >> 2;       // warps 4 x 2, 32x32 each
    const int m0 = blockIdx.y * 128, n0 = blockIdx.x * 64;

    float acc[2][4][4];
#pragma unroll
    for (int i = 0; i < 2; i++)
#pragma unroll
        for (int j = 0; j < 4; j++)
#pragma unroll
            for (int t = 0; t < 4; t++) acc[i][j][t] = 0.f;

    const uint32_t a_off = (uint32_t)((wm * 32 + (lane & 7) + ((lane >> 3) & 1) * 8) * MG_PIT
                                      + (lane >> 4) * 16);
    const uint32_t b_off = (uint32_t)((wn * 32 + ((lane >> 4) & 1) * 8 + (lane & 7)) * MG_PIT
                                      + ((lane >> 3) & 1) * 16);

    auto cpAB = [&](int c, int s) {
        const uint32_t base = sb + s * MG_STG;
        const size_t ko = (size_t)c * 32;
        {
            const int r = tid >> 1, h = tid & 1;
            const __half* a0 = A + (size_t)(m0 + r) * K + ko + h * 16;
            const uint32_t doff = base + OA + (uint32_t)(r * MG_PIT + h * 32);
            CP16(doff, a0); CP16(doff + 16, a0 + 8);
        }
        {
            const int r = tid >> 2, q = tid & 3;
            const __half* b0 = B + (size_t)(n0 + r) * K + ko + q * 8;
            CP16(base + OB + (uint32_t)(r * MG_PIT + q * 16), b0);
        }
        CP_COMMIT();
    };

    const int NC = K >> 5;
#pragma unroll
    for (int i = 0; i < 3; i++) {
        if (i < NC) cpAB(i, i);
        else        CP_COMMIT();
    }
    for (int c = 0; c < NC; c++) {
        const int s = c & (MG_NSTG - 1);
        CP_WAIT2();
        __syncthreads();
        if (c + 3 < NC) cpAB(c + 3, (c + 3) & (MG_NSTG - 1));
        else            CP_COMMIT();
        const uint32_t base = sb + s * MG_STG;
#pragma unroll
        for (int ks = 0; ks < 2; ks++) {
            const uint32_t koff = ks * 32;
            uint32_t a[2][4];
#pragma unroll
            for (int mi = 0; mi < 2; mi++)
                LDSM4(a[mi][0], a[mi][1], a[mi][2], a[mi][3],
                      base + OA + a_off + mi * (16 * MG_PIT) + koff);
#pragma unroll
            for (int np = 0; np < 2; np++) {
                uint32_t b[4];
                LDSM4(b[0], b[1], b[2], b[3],
                      base + OB + b_off + np * (16 * MG_PIT) + koff);
#pragma unroll
                for (int mi = 0; mi < 2; mi++) {
#pragma unroll
                    for (int t = 0; t < 2; t++) {
                        MMAF16(acc[mi][np * 2 + t], a[mi][0], a[mi][1], a[mi][2], a[mi][3],
                               b[2*t], b[2*t + 1]);
                    }
                }
            }
        }
    }
    CP_WAIT0();

    // epilogue
#pragma unroll
    for (int mi = 0; mi < 2; mi++) {
        const int r0 = m0 + wm * 32 + mi * 16 + (lane >> 2);
#pragma unroll
        for (int ni = 0; ni < 4; ni++) {
            const int col = n0 + wn * 32 + ni * 8 + 2 * (lane & 3);
            if (col >= Nout) continue;
            float v00 = acc[mi][ni][0], v01 = acc[mi][ni][1];
            float v10 = acc[mi][ni][2], v11 = acc[mi][ni][3];
            if (BIAS) {
                float2 bv = *(const float2*)&bias[col];
                v00 += bv.x; v01 += bv.y; v10 += bv.x; v11 += bv.y;
            }
            const size_t o0 = (size_t)r0 * Nout + col;
            const size_t o1 = (size_t)(r0 + 8) * Nout + col;
            const bool m0ok = (r0 < Mout), m1ok = (r0 + 8 < Mout);
            if (ADDC) {
                if (m0ok) {
                    __half2 c0 = *(const __half2*)&Cin[o0];
                    v00 += __half2float(c0.x); v01 += __half2float(c0.y);
                }
                if (m1ok) {
                    __half2 c1 = *(const __half2*)&Cin[o1];
                    v10 += __half2float(c1.x); v11 += __half2float(c1.y);
                }
            }
            if (RELU) {
                v00 = fmaxf(v00, 0.f); v01 = fmaxf(v01, 0.f);
                v10 = fmaxf(v10, 0.f); v11 = fmaxf(v11, 0.f);
            }
            if (OUTPL) {
                __half2 h0, h1;
                h0.x = __float2half_rn(v00); h0.y = __float2half_rn(v01);
                h1.x = __float2half_rn(v10); h1.y = __float2half_rn(v11);
                if (m0ok) *(__half2*)&Oh[o0] = h0;
                if (m1ok) *(__half2*)&Oh[o1] = h1;
            } else {
                if (m0ok) *(float2*)&C[o0] = make_float2(v00, v01);
                if (m1ok) *(float2*)&C[o1] = make_float2(v10, v11);
            }
        }
    }
}

template <int R, int AD, int BI, int OP>
static void mg2(const __half* A, const __half* B, const float* bias,
                const __half* Cin, float* C, __half* Oh,
                int M, int Npad, int K, int Nout, int Mout) {
    cudaFuncSetAttribute(mgemm_k<R, AD, BI, OP>,
                         cudaFuncAttributeMaxDynamicSharedMemorySize, MG_SMEM);
    dim3 g(Npad / 64, (M + 127) / 128);
    mgemm_k<R, AD, BI, OP><<<g, 256, MG_SMEM>>>(A, B, bias, Cin, C, Oh, K, Nout, Mout);
}

// ---------------------------------------------------------------------------
// Merged weight conversion (wq, wo, c1, c2, padded proj) — one launch
// ---------------------------------------------------------------------------
#define NW1 (2*DDIM*DDIM)   // 524288
#define NW2 (2*DFF*DDIM)    // 2097152
#define NWP (NPADP*KPADP)   // 5824512
#define NW_TOTAL (2*NW1 + 2*NW2 + NWP)

__global__ void cvt_all_k(const float* __restrict__ Wq, const float* __restrict__ Wo,
                          const float* __restrict__ C1, const float* __restrict__ C2,
                          const float* __restrict__ PW,
                          __half* __restrict__ wq, __half* __restrict__ wo,
                          __half* __restrict__ c1, __half* __restrict__ c2,
                          __half* __restrict__ pwh) {
    int i = blockIdx.x * blockDim.x + threadIdx.x;
    if (i < NW1) { wq[i] = __float2half_rn(Wq[i]); return; }
    i -= NW1;
    if (i < NW1) { wo[i] = __float2half_rn(Wo[i]); return; }
    i -= NW1;
    if (i < NW2) { c1[i] = __float2half_rn(C1[i]); return; }
    i -= NW2;
    if (i < NW2) { c2[i] = __float2half_rn(C2[i]); return; }
    i -= NW2;
    if (i < NWP) {
        int r = i / KPADP, c = i - r * KPADP;
        pwh[i] = (r < NAPP && c < KCAT) ? __float2half_rn(PW[(size_t)r * KCAT + c]) : __half(0.f);
    }
}

__global__ void init_tw_k(__half* tw, __half* itw) {
    int i = blockIdx.x * blockDim.x + threadIdx.x;   // 0..32767
    {
        int c = i >> 9, l = i & 511;
        double v;
        if (c < 32)  v = cos((TWOPI / 512.0) * (double)(l * c));
        else         v = -sin((TWOPI / 512.0) * (double)(l * (c - 32)));
        tw[i] = __float2half_rn((float)v);
    }
    {
        int l = i >> 6, c = i & 63;
        double v;
        if (c == 0)       v = 1.0 / 512.0;
        else if (c < 32)  v = 2.0 * cos((TWOPI / 512.0) * (double)(l * c)) / 512.0;
        else if (c == 32) v = 0.0;
        else              v = -2.0 * sin((TWOPI / 512.0) * (double)(l * (c - 32))) / 512.0;
        itw[i] = __float2half_rn((float)v);
    }
}

// ---------------------------------------------------------------------------
// Embedding -> fp16 plane
// ---------------------------------------------------------------------------
__global__ void embed_k(const int* __restrict__ x_app, const float* __restrict__ x_time,
                        const float* __restrict__ emb, const float* __restrict__ tw,
                        const float* __restrict__ tb, __half* __restrict__ px) {
    int b = blockIdx.y, l = blockIdx.x;
    int d = threadIdx.x * 2;
    int a = x_app[b * LL + l];
    float t = x_time[b * LL + l];
    size_t idx = ((size_t)b * LL + l) * DDIM + d;
    float2 e = *(const float2*)&emb[(size_t)a * DDIM + d];
    float2 w = *(const float2*)&tw[d];
    float2 bb = *(const float2*)&tb[d];
    __half2 h;
    h.x = __float2half_rn(e.x + t * w.x + bb.x);
    h.y = __float2half_rn(e.y + t * w.y + bb.y);
    *(__half2*)&px[idx] = h;
}

// ---------------------------------------------------------------------------
// Per-batch 512x512 transpose, fp16 -> fp16
// ---------------------------------------------------------------------------
__global__ void transpose_half_k(const __half* __restrict__ in, __half* __restrict__ out) {
    __shared__ __half tile[32][33];
    int b = blockIdx.z;
    const __half* ip = in + (size_t)b * (512 * 512);
    __half* op = out + (size_t)b * (512 * 512);
    int i0 = blockIdx.y * 32, j0 = blockIdx.x * 32;
#pragma unroll
    for (int r = 0; r < 32; r += 8)
        tile[threadIdx.y + r][threadIdx.x] =
            ip[(size_t)(i0 + threadIdx.y + r) * 512 + j0 + threadIdx.x];
    __syncthreads();
#pragma unroll
    for (int r = 0; r < 32; r += 8)
        op[(size_t)(j0 + threadIdx.y + r) * 512 + i0 + threadIdx.x] =
            tile[threadIdx.x][threadIdx.y + r];
}

// ---------------------------------------------------------------------------
// Mode transposes (per batch): [(b,d)512, m64] <-> [(b,m)64, d512]
// ---------------------------------------------------------------------------
__global__ void mtrans_fwd_k(const __half* __restrict__ in, __half* __restrict__ out) {
    __shared__ __half tile[32][33];
    int b = blockIdx.z;
    int m0 = blockIdx.x * 32, d0 = blockIdx.y * 32;
    const __half* ip = in + (size_t)b * 512 * 64;
    __half* op = out + (size_t)b * 64 * 512;
#pragma unroll
    for (int r = 0; r < 32; r += 8)
        tile[threadIdx.y + r][threadIdx.x] =
            ip[(size_t)(d0 + threadIdx.y + r) * 64 + m0 + threadIdx.x];
    __syncthreads();
#pragma unroll
    for (int r = 0; r < 32; r += 8)
        op[(size_t)(m0 + threadIdx.y + r) * 512 + d0 + threadIdx.x] =
            tile[threadIdx.x][threadIdx.y + r];
}

__global__ void mtrans_bwd_k(const __half* __restrict__ in, const float* __restrict__ bo,
                             __half* __restrict__ out) {
    __shared__ __half tile[32][33];
    int b = blockIdx.z;
    int d0 = blockIdx.x * 32, m0 = blockIdx.y * 32;
    const __half* ip = in + (size_t)b * 64 * 512;
    __half* op = out + (size_t)b * 512 * 64;
#pragma unroll
    for (int r = 0; r < 32; r += 8) {
        int m = m0 + threadIdx.y + r;
        float v = __half2float(ip[(size_t)m * 512 + d0 + threadIdx.x]);
        if (m == 0) v += 512.f * bo[d0 + threadIdx.x];
        tile[threadIdx.y + r][threadIdx.x] = __float2half_rn(v);
    }
    __syncthreads();
#pragma unroll
    for (int r = 0; r < 32; r += 8)
        op[(size_t)(d0 + threadIdx.y + r) * 64 + m0 + threadIdx.x] =
            tile[threadIdx.x][threadIdx.y + r];
}

// ---------------------------------------------------------------------------
// Complex mode mixing in [(b,m),d] layout (fp16 I/O); folds +512*bq at mode 0
// ---------------------------------------------------------------------------
__global__ void modemix_k(const __half* __restrict__ qft, const float* __restrict__ bq,
                          const float* __restrict__ wr, const float* __restrict__ wi,
                          __half* __restrict__ g) {
    int mode = blockIdx.x, h = blockIdx.y;
    __shared__ float Xr[64][32], Xi[64][32], Wr[32][64], Wi[32][64];
    int tid = threadIdx.x;
    int tb = tid >> 4, to = tid & 15;
    float cr[4][4], ci[4][4];
#pragma unroll
    for (int a = 0; a < 4; a++)
#pragma unroll
        for (int c = 0; c < 4; c++) { cr[a][c] = 0.f; ci[a][c] = 0.f; }
    for (int i0 = 0; i0 < 64; i0 += 32) {
#pragma unroll
        for (int j = 0; j < 8; j++) {
            int e = tid * 8 + j;
            int b = e >> 5, ii = e & 31;
            int dd = h * 64 + i0 + ii;
            float vr = __half2float(qft[((size_t)b * 64 + mode) * 512 + dd]);
            if (mode == 0) vr += 512.f * bq[dd];
            Xr[b][ii] = vr;
            Xi[b][ii] = __half2float(qft[((size_t)b * 64 + 32 + mode) * 512 + dd]);
            int wi2 = e >> 6, o = e & 63;
            size_t widx = (((size_t)h * 64 + i0 + wi2) * 64 + o) * 32 + mode;
            Wr[wi2][o] = wr[widx];
            Wi[wi2][o] = wi[widx];
        }
        __syncthreads();
#pragma unroll 8
        for (int ii = 0; ii < 32; ii++) {
            float xr[4], xi4[4], wrv[4], wiv[4];
#pragma unroll
            for (int a = 0; a < 4; a++) { xr[a] = Xr[tb*4+a][ii]; xi4[a] = Xi[tb*4+a][ii]; }
#pragma unroll
            for (int c = 0; c < 4; c++) { wrv[c] = Wr[ii][to*4+c]; wiv[c] = Wi[ii][to*4+c]; }
#pragma unroll
            for (int a = 0; a < 4; a++)
#pragma unroll
                for (int c = 0; c < 4; c++) {
                    cr[a][c] += xr[a] * wrv[c] - xi4[a] * wiv[c];
                    ci[a][c] += xr[a] * wiv[c] + xi4[a] * wrv[c];
                }
        }
        __syncthreads();
    }
#pragma unroll
    for (int a = 0; a < 4; a++) {
        int b = tb * 4 + a;
#pragma unroll
        for (int c = 0; c < 4; c++) {
            int o = to * 4 + c;
            int dd = h * 64 + o;
            g[((size_t)b * 64 + mode) * 512 + dd] = __float2half_rn(cr[a][c]);
            g[((size_t)b * 64 + 32 + mode) * 512 + dd] = __float2half_rn(ci[a][c]);
        }
    }
}

// ---------------------------------------------------------------------------
// Series decomposition: rolling 25-window, fp16 in -> fp16 out ([b,l,d])
// ---------------------------------------------------------------------------
__global__ void decomp_k(const __half* __restrict__ in, __half* __restrict__ out) {
    int b = blockIdx.z;
    int d = blockIdx.x * 128 + threadIdx.x;
    int l0 = blockIdx.y * 64;
    const __half* p = in + (size_t)b * (LL * DDIM) + d;
    float sum = 0.f;
#pragma unroll
    for (int j = -12; j <= 12; j++) {
        int t = l0 + j;
        t = t < 0 ? 0 : (t > 511 ? 511 : t);
        sum += __half2float(p[(size_t)t * DDIM]);
    }
    size_t obase = (size_t)b * (LL * DDIM) + d;
    for (int l = l0; l < l0 + 64; l++) {
        float v = __half2float(p[(size_t)l * DDIM]) - sum * (1.0f / 25.0f);
        out[obase + (size_t)l * DDIM] = __float2half_rn(v);
        int jn = l + 13 > 511 ? 511 : l + 13;
        int jo = l - 12 < 0 ? 0 : l - 12;
        sum += __half2float(p[(size_t)jn * DDIM]) - __half2float(p[(size_t)jo * DDIM]);
    }
}

// ---------------------------------------------------------------------------
// LayerNorm stats only (mu, rs per (b,l)) — xh never materialized
// ---------------------------------------------------------------------------
__device__ __forceinline__ float blocksum512(float v, float* red) {
    int lane = threadIdx.x & 31, w = threadIdx.x >> 5;
#pragma unroll
    for (int o = 16; o; o >>= 1) v += __shfl_down_sync(0xffffffffu, v, o);
    if (lane == 0) red[w] = v;
    __syncthreads();
    if (w == 0) {
        float t = (lane < 16) ? red[lane] : 0.f;
#pragma unroll
        for (int o = 8; o; o >>= 1) t += __shfl_down_sync(0xffffffffu, t, o);
        if (lane == 0) red[0] = t;
    }
    __syncthreads();
    float r = red[0];
    __syncthreads();
    return r;
}

__global__ void ln_stats_k(const __half* __restrict__ x, float2* __restrict__ st) {
    __shared__ float red[32];
    int b = blockIdx.y, l = blockIdx.x, d = threadIdx.x;
    size_t base = ((size_t)b * LL + l) * DDIM;
    float v = __half2float(x[base + d]);
    float mu = blocksum512(v, red) * (1.f / 512.f);
    float dv = v - mu;
    float var = blocksum512(dv * dv, red) * (1.f / 512.f);
    if (d == 0) st[(size_t)b * LL + l] = make_float2(mu, rsqrtf(var + 1e-5f));
}

// 8 partial sums per (b,d) of (x - mu_l)*rs_l
__global__ void partial_sum_k(const __half* __restrict__ x, const float2* __restrict__ st,
                              float* __restrict__ acc) {
    __shared__ float2 s[64];
    int b = blockIdx.y, d = threadIdx.x, part = blockIdx.x;
    int l0 = part * 64;
    if (d < 64) s[d] = st[(size_t)b * LL + l0 + d];
    __syncthreads();
    float sum = 0.f;
    for (int i = 0; i < 64; i++) {
        float2 mr = s[i];
        sum += (__half2float(x[((size_t)b * LL + l0 + i) * DDIM + d]) - mr.x) * mr.y;
    }
    acc[((size_t)part * BB + b) * DDIM + d] = sum;
}

// Final concat: cat[b][d] = w[d]*((x511-mu)*rs - sum/512); pads rows/cols with 0
__global__ void lastcat_k(const __half* __restrict__ x, const float2* __restrict__ st,
                          const float* __restrict__ acc, const float* __restrict__ w,
                          const float* __restrict__ time_vecs, __half* __restrict__ cath) {
    int b = blockIdx.x, d = threadIdx.x;   // grid 128, block KPADP(576)
    float out = 0.f;
    if (b < BB) {
        if (d < DDIM) {
            float s = 0.f;
#pragma unroll
            for (int p = 0; p < 8; p++) s += acc[((size_t)p * BB + b) * DDIM + d];
            float2 mr = st[(size_t)b * LL + 511];
            float v = (__half2float(x[((size_t)b * LL + 511) * DDIM + d]) - mr.x) * mr.y;
            out = w[d] * (v - s * (1.f / 512.f));
        } else if (d < KCAT) {
            out = time_vecs[((size_t)b * LL + 511) * 24 + (d - 512)];
        }
    }
    cath[b * KPADP + d] = __float2half_rn(out);
}

// ---------------------------------------------------------------------------
// Host orchestration
// ---------------------------------------------------------------------------
extern "C" void kernel_launch(void* const* d_in, const int* in_sizes, int n_in,
                              void* d_out, int out_size) {
    (void)in_sizes; (void)n_in; (void)out_size;
    const int*   x_app     = (const int*)  d_in[0];
    const float* x_time    = (const float*)d_in[1];
    const float* time_vecs = (const float*)d_in[2];
    const float* emb       = (const float*)d_in[4];
    const float* time_w    = (const float*)d_in[5];
    const float* time_b    = (const float*)d_in[6];
    const float* Wq        = (const float*)d_in[7];
    const float* bq        = (const float*)d_in[8];
    const float* Wo        = (const float*)d_in[9];
    const float* bo        = (const float*)d_in[10];
    const float* four_wr   = (const float*)d_in[11];
    const float* four_wi   = (const float*)d_in[12];
    const float* conv1     = (const float*)d_in[13];
    const float* conv2     = (const float*)d_in[14];
    const float* norm_w    = (const float*)d_in[15];
    /* norm_b cancels in cat = xh[511] - mean_L(xh) */
    const float* proj_w    = (const float*)d_in[17];
    const float* proj_b    = (const float*)d_in[18];

    float *gacc;
    float2 *gst;
    __half *pa, *pb, *px, *pxt, *yp, *wq, *wo, *c1, *c2, *tw, *itw, *cath, *pwh;
    cudaGetSymbolAddress((void**)&gacc, g_acc);
    cudaGetSymbolAddress((void**)&gst,  g_st);
    cudaGetSymbolAddress((void**)&pa,   g_pa);
    cudaGetSymbolAddress((void**)&pb,   g_pb);
    cudaGetSymbolAddress((void**)&px,   g_px);
    cudaGetSymbolAddress((void**)&pxt,  g_pxt);
    cudaGetSymbolAddress((void**)&yp,   g_yp);
    cudaGetSymbolAddress((void**)&wq,   g_wq);
    cudaGetSymbolAddress((void**)&wo,   g_wo);
    cudaGetSymbolAddress((void**)&c1,   g_c1);
    cudaGetSymbolAddress((void**)&c2,   g_c2);
    cudaGetSymbolAddress((void**)&tw,   g_tw);
    cudaGetSymbolAddress((void**)&itw,  g_itw);
    cudaGetSymbolAddress((void**)&cath, g_cath);
    cudaGetSymbolAddress((void**)&pwh,  g_pwh);

    const int M = MTOT;   // 32768

    init_tw_k<<<128, 256>>>(tw, itw);
    cvt_all_k<<<(NW_TOTAL + 255) / 256, 256>>>(Wq, Wo, conv1, conv2, proj_w,
                                               wq, wo, c1, c2, pwh);
    embed_k<<<dim3(LL, BB), 256>>>(x_app, x_time, emb, time_w, time_b, px);

    dim3 tgrid(16, 16, BB), tblk(32, 8);
    dim3 mfgrid(2, 16, BB);   // mtrans_fwd
    dim3 mbgrid(16, 2, BB);   // mtrans_bwd
    dim3 dgrid(4, 8, BB);

    for (int l = 0; l < 2; l++) {
        const float* bql = bq + (size_t)l * DDIM;
        const float* bol = bo + (size_t)l * DDIM;
        const float* wrl = four_wr + (size_t)l * HH * EE * EE * NMODES;
        const float* wil = four_wi + (size_t)l * HH * EE * EE * NMODES;
        size_t owq = (size_t)l * DDIM * DDIM;
        size_t oc1 = (size_t)l * DFF * DDIM;
        size_t oc2 = (size_t)l * DDIM * DFF;

        // xT = transpose(x): px -> pxt
        transpose_half_k<<<tgrid, tblk>>>(px, pxt);
        // fwd DFT: Xft[(b,d),m] = xT @ TW^T
        mg2<0,0,0,1>(pxt, tw, nullptr, nullptr, nullptr, pa, M, 64, 512, 64, M);
        // Xft -> [(b,m),d]
        mtrans_fwd_k<<<mfgrid, tblk>>>(pa, pb);
        // q_ft = Xft @ Wq^T  (mode space: M=4096)
        mg2<0,0,0,1>(pb, wq + owq, nullptr, nullptr, nullptr, pa, MMODE, 512, 512, 512, MMODE);
        // complex mode mixing (+512*bq at DC)
        modemix_k<<<dim3(NMODES, HH), 256>>>(pa, bql, wrl, wil, pb);
        // G' = G @ Wo^T  (mode space)
        mg2<0,0,0,1>(pb, wo + owq, nullptr, nullptr, nullptr, pa, MMODE, 512, 512, 512, MMODE);
        // G' -> [(b,d),m], +512*bo at DC
        mtrans_bwd_k<<<mbgrid, tblk>>>(pa, bol, pb);
        // inv DFT + residual: tmpT[(b,d),l] = G'T @ ITW^T + xT  (K=64)
        mg2<0,1,0,1>(pb, itw, nullptr, pxt, nullptr, pa, M, 512, 64, 512, M);
        // tmpT -> tmp [b,l,d]
        transpose_half_k<<<tgrid, tblk>>>(pa, pb);
        // x = tmp - movavg(tmp)
        decomp_k<<<dgrid, 128>>>(pb, px);
        // y = relu(x @ c1^T)
        mg2<1,0,0,1>(px, c1 + oc1, nullptr, nullptr, nullptr, yp, M, 2048, 512, 2048, M);
        // tmp = y @ c2^T + x
        mg2<0,1,0,1>(yp, c2 + oc2, nullptr, px, nullptr, pb, M, 512, 2048, 512, M);
        // x = tmp - movavg(tmp)
        decomp_k<<<dgrid, 128>>>(pb, px);
    }

    // fused final layernorm (stats-only) + concat
    ln_stats_k<<<dim3(LL, BB), DDIM>>>(px, gst);
    partial_sum_k<<<dim3(8, BB), DDIM>>>(px, gst, gacc);
    lastcat_k<<<128, KPADP>>>(px, gst, gacc, norm_w, time_vecs, cath);
    // score = cat @ proj_w^T + proj_b  (f32 out, Mout=64)
    mg2<0,0,1,0>(cath, pwh, proj_b, nullptr, (float*)d_out, nullptr,
                 128, NPADP, KPADP, NAPP, BB);
}

// round 16
// speedup vs baseline: 1.0490x; 1.0265x over previous
#include <cuda_runtime.h>
#include <cuda_fp16.h>
#include <math.h>
#include <stdint.h>

// Problem constants
#define BB    64
#define LL    512
#define DDIM  512
#define HH    8
#define EE    64
#define DFF   2048
#define NMODES 32
#define NAPP  10000
#define KCAT  536    // D + 24
#define MTOT  (BB*LL)
#define MMODE (BB*64)   // 4096 mode-rows (32 re + 32 im per batch)
#define NPADP 10112  // proj N padded (mult of 64)
#define KPADP 576    // proj K padded (mult of 32)
#define TWOPI 6.283185307179586476925286766559

// ---------------------------------------------------------------------------
// Scratch (device globals — no runtime allocation allowed)
// ---------------------------------------------------------------------------
__device__ __align__(128) float g_acc[8*BB*DDIM];    // 8 partial sums per (b,d)
__device__ __align__(128) float2 g_st[MTOT];         // layernorm stats (mu, rs)

// fp16 activation planes
__device__ __align__(128) __half g_pa [MTOT*DDIM];
__device__ __align__(128) __half g_pb [MTOT*DDIM];
__device__ __align__(128) __half g_px [MTOT*DDIM];   // residual x [b,l,d]
__device__ __align__(128) __half g_pxt[MTOT*DDIM];   // x transposed [b,d,l]
__device__ __align__(128) __half g_yp [MTOT*DFF];
// fp16 weights / twiddles
__device__ __align__(128) __half g_wq [2*DDIM*DDIM];
__device__ __align__(128) __half g_wo [2*DDIM*DDIM];
__device__ __align__(128) __half g_c1 [2*DFF*DDIM];
__device__ __align__(128) __half g_c2 [2*DDIM*DFF];
__device__ __align__(128) __half g_tw [64*512];      // fwd DFT (32 re + 32 im rows)
__device__ __align__(128) __half g_itw[512*64];      // inv DFT
__device__ __align__(128) __half g_cath[128*KPADP];  // padded cat (fp16)
__device__ __align__(128) __half g_pwh[NPADP*KPADP]; // padded proj weights (fp16)

// ---------------------------------------------------------------------------
// PTX helpers
// ---------------------------------------------------------------------------
__device__ __forceinline__ uint32_t smem_u32(const void* p) {
    uint32_t a;
    asm("{ .reg .u64 t; cvta.to.shared.u64 t, %1; cvt.u32.u64 %0, t; }" : "=r"(a) : "l"(p));
    return a;
}
#define CP16(d, s)  asm volatile("cp.async.cg.shared.global [%0], [%1], 16;" :: "r"(d), "l"(s) : "memory")
#define CP_COMMIT() asm volatile("cp.async.commit_group;" ::: "memory")
#define CP_WAIT2()  asm volatile("cp.async.wait_group 2;" ::: "memory")
#define CP_WAIT0()  asm volatile("cp.async.wait_group 0;" ::: "memory")

#define LDSM4(r0, r1, r2, r3, a) \
    asm volatile("ldmatrix.sync.aligned.m8n8.x4.shared.b16 {%0,%1,%2,%3}, [%4];" \
        : "=r"(r0), "=r"(r1), "=r"(r2), "=r"(r3) : "r"(a))

#define MMAF16(c, a0, a1, a2, a3, b0, b1) \
    asm volatile("mma.sync.aligned.m16n8k16.row.col.f32.f16.f16.f32 " \
        "{%0,%1,%2,%3}, {%4,%5,%6,%7}, {%8,%9}, {%0,%1,%2,%3};" \
        : "+f"((c)[0]), "+f"((c)[1]), "+f"((c)[2]), "+f"((c)[3]) \
        : "r"(a0), "r"(a1), "r"(a2), "r"(a3), "r"(b0), "r"(b1))

// ---------------------------------------------------------------------------
// Tensor-core GEMM (fp16 x fp16 -> fp32 accum): C[m,n] = sum_k A[m,k]*B[n,k]
//   CTA tile 128x64, 256 threads (8 warps, 4m x 2n), warp tile 32x32.
//   BK=32, 80B pitch, 4-stage cp.async, 3 CTAs/SM.
// ---------------------------------------------------------------------------
#define MG_PIT  80
#define MG_PLA  (128 * MG_PIT)
#define MG_PLB  (64 * MG_PIT)
#define MG_STG  (MG_PLA + MG_PLB)    // 15360 B
#define MG_NSTG 4
#define MG_SMEM (MG_NSTG * MG_STG)   // 61440 B
#define OA 0
#define OB MG_PLA

template <int RELU, int ADDC, int BIAS, int OUTPL>
__global__ void __launch_bounds__(256, 3)
mgemm_k(const __half* __restrict__ A, const __half* __restrict__ B,
        const float* __restrict__ bias, const __half* __restrict__ Cin,
        float* __restrict__ C, __half* __restrict__ Oh, int K, int Nout, int Mout) {
    extern __shared__ __align__(128) char smem[];
    const uint32_t sb = smem_u32(smem);
    const int tid = threadIdx.x, lane = tid & 31, wid = tid >> 5;
    const int wm = wid & 3, wn = wid >> 2;       // warps 4 x 2, 32x32 each
    const int m0 = blockIdx.y * 128, n0 = blockIdx.x * 64;

    float acc[2][4][4];
#pragma unroll
    for (int i = 0; i < 2; i++)
#pragma unroll
        for (int j = 0; j < 4; j++)
#pragma unroll
            for (int t = 0; t < 4; t++) acc[i][j][t] = 0.f;

    const uint32_t a_off = (uint32_t)((wm * 32 + (lane & 7) + ((lane >> 3) & 1) * 8) * MG_PIT
                                      + (lane >> 4) * 16);
    const uint32_t b_off = (uint32_t)((wn * 32 + ((lane >> 4) & 1) * 8 + (lane & 7)) * MG_PIT
                                      + ((lane >> 3) & 1) * 16);

    auto cpAB = [&](int c, int s) {
        const uint32_t base = sb + s * MG_STG;
        const size_t ko = (size_t)c * 32;
        {
            const int r = tid >> 1, h = tid & 1;
            const __half* a0 = A + (size_t)(m0 + r) * K + ko + h * 16;
            const uint32_t doff = base + OA + (uint32_t)(r * MG_PIT + h * 32);
            CP16(doff, a0); CP16(doff + 16, a0 + 8);
        }
        {
            const int r = tid >> 2, q = tid & 3;
            const __half* b0 = B + (size_t)(n0 + r) * K + ko + q * 8;
            CP16(base + OB + (uint32_t)(r * MG_PIT + q * 16), b0);
        }
        CP_COMMIT();
    };

    const int NC = K >> 5;
#pragma unroll
    for (int i = 0; i < 3; i++) {
        if (i < NC) cpAB(i, i);
        else        CP_COMMIT();
    }
    for (int c = 0; c < NC; c++) {
        const int s = c & (MG_NSTG - 1);
        CP_WAIT2();
        __syncthreads();
        if (c + 3 < NC) cpAB(c + 3, (c + 3) & (MG_NSTG - 1));
        else            CP_COMMIT();
        const uint32_t base = sb + s * MG_STG;
#pragma unroll
        for (int ks = 0; ks < 2; ks++) {
            const uint32_t koff = ks * 32;
            uint32_t a[2][4];
#pragma unroll
            for (int mi = 0; mi < 2; mi++)
                LDSM4(a[mi][0], a[mi][1], a[mi][2], a[mi][3],
                      base + OA + a_off + mi * (16 * MG_PIT) + koff);
#pragma unroll
            for (int np = 0; np < 2; np++) {
                uint32_t b[4];
                LDSM4(b[0], b[1], b[2], b[3],
                      base + OB + b_off + np * (16 * MG_PIT) + koff);
#pragma unroll
                for (int mi = 0; mi < 2; mi++) {
#pragma unroll
                    for (int t = 0; t < 2; t++) {
                        MMAF16(acc[mi][np * 2 + t], a[mi][0], a[mi][1], a[mi][2], a[mi][3],
                               b[2*t], b[2*t + 1]);
                    }
                }
            }
        }
    }
    CP_WAIT0();

    // epilogue
#pragma unroll
    for (int mi = 0; mi < 2; mi++) {
        const int r0 = m0 + wm * 32 + mi * 16 + (lane >> 2);
#pragma unroll
        for (int ni = 0; ni < 4; ni++) {
            const int col = n0 + wn * 32 + ni * 8 + 2 * (lane & 3);
            if (col >= Nout) continue;
            float v00 = acc[mi][ni][0], v01 = acc[mi][ni][1];
            float v10 = acc[mi][ni][2], v11 = acc[mi][ni][3];
            if (BIAS) {
                float2 bv = *(const float2*)&bias[col];
                v00 += bv.x; v01 += bv.y; v10 += bv.x; v11 += bv.y;
            }
            const size_t o0 = (size_t)r0 * Nout + col;
            const size_t o1 = (size_t)(r0 + 8) * Nout + col;
            const bool m0ok = (r0 < Mout), m1ok = (r0 + 8 < Mout);
            if (ADDC) {
                if (m0ok) {
                    __half2 c0 = *(const __half2*)&Cin[o0];
                    v00 += __half2float(c0.x); v01 += __half2float(c0.y);
                }
                if (m1ok) {
                    __half2 c1 = *(const __half2*)&Cin[o1];
                    v10 += __half2float(c1.x); v11 += __half2float(c1.y);
                }
            }
            if (RELU) {
                v00 = fmaxf(v00, 0.f); v01 = fmaxf(v01, 0.f);
                v10 = fmaxf(v10, 0.f); v11 = fmaxf(v11, 0.f);
            }
            if (OUTPL) {
                __half2 h0, h1;
                h0.x = __float2half_rn(v00); h0.y = __float2half_rn(v01);
                h1.x = __float2half_rn(v10); h1.y = __float2half_rn(v11);
                if (m0ok) *(__half2*)&Oh[o0] = h0;
                if (m1ok) *(__half2*)&Oh[o1] = h1;
            } else {
                if (m0ok) *(float2*)&C[o0] = make_float2(v00, v01);
                if (m1ok) *(float2*)&C[o1] = make_float2(v10, v11);
            }
        }
    }
}

template <int R, int AD, int BI, int OP>
static void mg2(const __half* A, const __half* B, const float* bias,
                const __half* Cin, float* C, __half* Oh,
                int M, int Npad, int K, int Nout, int Mout) {
    cudaFuncSetAttribute(mgemm_k<R, AD, BI, OP>,
                         cudaFuncAttributeMaxDynamicSharedMemorySize, MG_SMEM);
    dim3 g(Npad / 64, (M + 127) / 128);
    mgemm_k<R, AD, BI, OP><<<g, 256, MG_SMEM>>>(A, B, bias, Cin, C, Oh, K, Nout, Mout);
}

// ---------------------------------------------------------------------------
// Merged weight conversion (wq, wo, c1, c2, padded proj) — one launch
// ---------------------------------------------------------------------------
#define NW1 (2*DDIM*DDIM)   // 524288
#define NW2 (2*DFF*DDIM)    // 2097152
#define NWP (NPADP*KPADP)   // 5824512
#define NW_TOTAL (2*NW1 + 2*NW2 + NWP)

__global__ void cvt_all_k(const float* __restrict__ Wq, const float* __restrict__ Wo,
                          const float* __restrict__ C1, const float* __restrict__ C2,
                          const float* __restrict__ PW,
                          __half* __restrict__ wq, __half* __restrict__ wo,
                          __half* __restrict__ c1, __half* __restrict__ c2,
                          __half* __restrict__ pwh) {
    int i = blockIdx.x * blockDim.x + threadIdx.x;
    if (i < NW1) { wq[i] = __float2half_rn(Wq[i]); return; }
    i -= NW1;
    if (i < NW1) { wo[i] = __float2half_rn(Wo[i]); return; }
    i -= NW1;
    if (i < NW2) { c1[i] = __float2half_rn(C1[i]); return; }
    i -= NW2;
    if (i < NW2) { c2[i] = __float2half_rn(C2[i]); return; }
    i -= NW2;
    if (i < NWP) {
        int r = i / KPADP, c = i - r * KPADP;
        pwh[i] = (r < NAPP && c < KCAT) ? __float2half_rn(PW[(size_t)r * KCAT + c]) : __half(0.f);
    }
}

__global__ void init_tw_k(__half* tw, __half* itw) {
    int i = blockIdx.x * blockDim.x + threadIdx.x;   // 0..32767
    {
        int c = i >> 9, l = i & 511;
        double v;
        if (c < 32)  v = cos((TWOPI / 512.0) * (double)(l * c));
        else         v = -sin((TWOPI / 512.0) * (double)(l * (c - 32)));
        tw[i] = __float2half_rn((float)v);
    }
    {
        int l = i >> 6, c = i & 63;
        double v;
        if (c == 0)       v = 1.0 / 512.0;
        else if (c < 32)  v = 2.0 * cos((TWOPI / 512.0) * (double)(l * c)) / 512.0;
        else if (c == 32) v = 0.0;
        else              v = -2.0 * sin((TWOPI / 512.0) * (double)(l * (c - 32))) / 512.0;
        itw[i] = __float2half_rn((float)v);
    }
}

// ---------------------------------------------------------------------------
// Embedding -> fp16 plane
// ---------------------------------------------------------------------------
__global__ void embed_k(const int* __restrict__ x_app, const float* __restrict__ x_time,
                        const float* __restrict__ emb, const float* __restrict__ tw,
                        const float* __restrict__ tb, __half* __restrict__ px) {
    int b = blockIdx.y, l = blockIdx.x;
    int d = threadIdx.x * 2;
    int a = x_app[b * LL + l];
    float t = x_time[b * LL + l];
    size_t idx = ((size_t)b * LL + l) * DDIM + d;
    float2 e = *(const float2*)&emb[(size_t)a * DDIM + d];
    float2 w = *(const float2*)&tw[d];
    float2 bb = *(const float2*)&tb[d];
    __half2 h;
    h.x = __float2half_rn(e.x + t * w.x + bb.x);
    h.y = __float2half_rn(e.y + t * w.y + bb.y);
    *(__half2*)&px[idx] = h;
}

// ---------------------------------------------------------------------------
// Per-batch 512x512 transpose, fp16, 64x64 tile, half2 loads AND stores.
//   block (32,8); smem [64][65] halfs (odd pitch -> conflict-free scalars).
// ---------------------------------------------------------------------------
__global__ void transpose64_k(const __half* __restrict__ in, __half* __restrict__ out) {
    __shared__ __half s[64][65];
    const int b = blockIdx.z;
    const int i0 = blockIdx.y * 64, j0 = blockIdx.x * 64;
    const __half* ip = in + (size_t)b * (512 * 512);
    __half* op = out + (size_t)b * (512 * 512);
    const int x = threadIdx.x, y = threadIdx.y;
#pragma unroll
    for (int r = 0; r < 64; r += 8) {
        __half2 v = *(const __half2*)&ip[(size_t)(i0 + r + y) * 512 + j0 + 2 * x];
        s[2 * x][r + y] = v.x;
        s[2 * x + 1][r + y] = v.y;
    }
    __syncthreads();
#pragma unroll
    for (int c = 0; c < 64; c += 8) {
        __half2 v;
        v.x = s[c + y][2 * x];
        v.y = s[c + y][2 * x + 1];
        *(__half2*)&op[(size_t)(j0 + c + y) * 512 + i0 + 2 * x] = v;
    }
}

// ---------------------------------------------------------------------------
// Mode transposes (per batch): [(b,d)512, m64] <-> [(b,m)64, d512]
// ---------------------------------------------------------------------------
__global__ void mtrans_fwd_k(const __half* __restrict__ in, __half* __restrict__ out) {
    __shared__ __half tile[32][33];
    int b = blockIdx.z;
    int m0 = blockIdx.x * 32, d0 = blockIdx.y * 32;
    const __half* ip = in + (size_t)b * 512 * 64;
    __half* op = out + (size_t)b * 64 * 512;
#pragma unroll
    for (int r = 0; r < 32; r += 8)
        tile[threadIdx.y + r][threadIdx.x] =
            ip[(size_t)(d0 + threadIdx.y + r) * 64 + m0 + threadIdx.x];
    __syncthreads();
#pragma unroll
    for (int r = 0; r < 32; r += 8)
        op[(size_t)(m0 + threadIdx.y + r) * 512 + d0 + threadIdx.x] =
            tile[threadIdx.x][threadIdx.y + r];
}

__global__ void mtrans_bwd_k(const __half* __restrict__ in, const float* __restrict__ bo,
                             __half* __restrict__ out) {
    __shared__ __half tile[32][33];
    int b = blockIdx.z;
    int d0 = blockIdx.x * 32, m0 = blockIdx.y * 32;
    const __half* ip = in + (size_t)b * 64 * 512;
    __half* op = out + (size_t)b * 512 * 64;
#pragma unroll
    for (int r = 0; r < 32; r += 8) {
        int m = m0 + threadIdx.y + r;
        float v = __half2float(ip[(size_t)m * 512 + d0 + threadIdx.x]);
        if (m == 0) v += 512.f * bo[d0 + threadIdx.x];
        tile[threadIdx.y + r][threadIdx.x] = __float2half_rn(v);
    }
    __syncthreads();
#pragma unroll
    for (int r = 0; r < 32; r += 8)
        op[(size_t)(d0 + threadIdx.y + r) * 64 + m0 + threadIdx.x] =
            tile[threadIdx.x][threadIdx.y + r];
}

// ---------------------------------------------------------------------------
// Complex mode mixing in [(b,m),d] layout (fp16 I/O); folds +512*bq at mode 0
// ---------------------------------------------------------------------------
__global__ void modemix_k(const __half* __restrict__ qft, const float* __restrict__ bq,
                          const float* __restrict__ wr, const float* __restrict__ wi,
                          __half* __restrict__ g) {
    int mode = blockIdx.x, h = blockIdx.y;
    __shared__ float Xr[64][32], Xi[64][32], Wr[32][64], Wi[32][64];
    int tid = threadIdx.x;
    int tb = tid >> 4, to = tid & 15;
    float cr[4][4], ci[4][4];
#pragma unroll
    for (int a = 0; a < 4; a++)
#pragma unroll
        for (int c = 0; c < 4; c++) { cr[a][c] = 0.f; ci[a][c] = 0.f; }
    for (int i0 = 0; i0 < 64; i0 += 32) {
#pragma unroll
        for (int j = 0; j < 8; j++) {
            int e = tid * 8 + j;
            int b = e >> 5, ii = e & 31;
            int dd = h * 64 + i0 + ii;
            float vr = __half2float(qft[((size_t)b * 64 + mode) * 512 + dd]);
            if (mode == 0) vr += 512.f * bq[dd];
            Xr[b][ii] = vr;
            Xi[b][ii] = __half2float(qft[((size_t)b * 64 + 32 + mode) * 512 + dd]);
            int wi2 = e >> 6, o = e & 63;
            size_t widx = (((size_t)h * 64 + i0 + wi2) * 64 + o) * 32 + mode;
            Wr[wi2][o] = wr[widx];
            Wi[wi2][o] = wi[widx];
        }
        __syncthreads();
#pragma unroll 8
        for (int ii = 0; ii < 32; ii++) {
            float xr[4], xi4[4], wrv[4], wiv[4];
#pragma unroll
            for (int a = 0; a < 4; a++) { xr[a] = Xr[tb*4+a][ii]; xi4[a] = Xi[tb*4+a][ii]; }
#pragma unroll
            for (int c = 0; c < 4; c++) { wrv[c] = Wr[ii][to*4+c]; wiv[c] = Wi[ii][to*4+c]; }
#pragma unroll
            for (int a = 0; a < 4; a++)
#pragma unroll
                for (int c = 0; c < 4; c++) {
                    cr[a][c] += xr[a] * wrv[c] - xi4[a] * wiv[c];
                    ci[a][c] += xr[a] * wiv[c] + xi4[a] * wrv[c];
                }
        }
        __syncthreads();
    }
#pragma unroll
    for (int a = 0; a < 4; a++) {
        int b = tb * 4 + a;
#pragma unroll
        for (int c = 0; c < 4; c++) {
            int o = to * 4 + c;
            int dd = h * 64 + o;
            g[((size_t)b * 64 + mode) * 512 + dd] = __float2half_rn(cr[a][c]);
            g[((size_t)b * 64 + 32 + mode) * 512 + dd] = __float2half_rn(ci[a][c]);
        }
    }
}

// ---------------------------------------------------------------------------
// Series decomposition: rolling 25-window, half2-vectorized over d
//   grid (2, 8, BB), block 128: each thread owns one half2 column.
// ---------------------------------------------------------------------------
__global__ void decomp_k(const __half* __restrict__ in, __half* __restrict__ out) {
    int b = blockIdx.z;
    int d2 = blockIdx.x * 128 + threadIdx.x;   // half2 index 0..255
    int l0 = blockIdx.y * 64;
    const __half2* p = (const __half2*)(in + (size_t)b * (LL * DDIM)) + d2;
    float sx = 0.f, sy = 0.f;
#pragma unroll
    for (int j = -12; j <= 12; j++) {
        int t = l0 + j;
        t = t < 0 ? 0 : (t > 511 ? 511 : t);
        __half2 h = p[(size_t)t * 256];
        sx += __half2float(h.x); sy += __half2float(h.y);
    }
    __half2* o = (__half2*)(out + (size_t)b * (LL * DDIM)) + d2;
    for (int l = l0; l < l0 + 64; l++) {
        __half2 hc = p[(size_t)l * 256];
        __half2 hv;
        hv.x = __float2half_rn(__half2float(hc.x) - sx * (1.f / 25.f));
        hv.y = __float2half_rn(__half2float(hc.y) - sy * (1.f / 25.f));
        o[(size_t)l * 256] = hv;
        int jn = l + 13 > 511 ? 511 : l + 13;
        int jo = l - 12 < 0 ? 0 : l - 12;
        __half2 hn = p[(size_t)jn * 256], ho = p[(size_t)jo * 256];
        sx += __half2float(hn.x) - __half2float(ho.x);
        sy += __half2float(hn.y) - __half2float(ho.y);
    }
}

// ---------------------------------------------------------------------------
// LayerNorm stats only (mu, rs per (b,l)) — xh never materialized
// ---------------------------------------------------------------------------
__device__ __forceinline__ float blocksum512(float v, float* red) {
    int lane = threadIdx.x & 31, w = threadIdx.x >> 5;
#pragma unroll
    for (int o = 16; o; o >>= 1) v += __shfl_down_sync(0xffffffffu, v, o);
    if (lane == 0) red[w] = v;
    __syncthreads();
    if (w == 0) {
        float t = (lane < 16) ? red[lane] : 0.f;
#pragma unroll
        for (int o = 8; o; o >>= 1) t += __shfl_down_sync(0xffffffffu, t, o);
        if (lane == 0) red[0] = t;
    }
    __syncthreads();
    float r = red[0];
    __syncthreads();
    return r;
}

__global__ void ln_stats_k(const __half* __restrict__ x, float2* __restrict__ st) {
    __shared__ float red[32];
    int b = blockIdx.y, l = blockIdx.x, d = threadIdx.x;
    size_t base = ((size_t)b * LL + l) * DDIM;
    float v = __half2float(x[base + d]);
    float mu = blocksum512(v, red) * (1.f / 512.f);
    float dv = v - mu;
    float var = blocksum512(dv * dv, red) * (1.f / 512.f);
    if (d == 0) st[(size_t)b * LL + l] = make_float2(mu, rsqrtf(var + 1e-5f));
}

// 8 partial sums per (b,d) of (x - mu_l)*rs_l
__global__ void partial_sum_k(const __half* __restrict__ x, const float2* __restrict__ st,
                              float* __restrict__ acc) {
    __shared__ float2 s[64];
    int b = blockIdx.y, d = threadIdx.x, part = blockIdx.x;
    int l0 = part * 64;
    if (d < 64) s[d] = st[(size_t)b * LL + l0 + d];
    __syncthreads();
    float sum = 0.f;
    for (int i = 0; i < 64; i++) {
        float2 mr = s[i];
        sum += (__half2float(x[((size_t)b * LL + l0 + i) * DDIM + d]) - mr.x) * mr.y;
    }
    acc[((size_t)part * BB + b) * DDIM + d] = sum;
}

// Final concat: cat[b][d] = w[d]*((x511-mu)*rs - sum/512); pads rows/cols with 0
__global__ void lastcat_k(const __half* __restrict__ x, const float2* __restrict__ st,
                          const float* __restrict__ acc, const float* __restrict__ w,
                          const float* __restrict__ time_vecs, __half* __restrict__ cath) {
    int b = blockIdx.x, d = threadIdx.x;   // grid 128, block KPADP(576)
    float out = 0.f;
    if (b < BB) {
        if (d < DDIM) {
            float s = 0.f;
#pragma unroll
            for (int p = 0; p < 8; p++) s += acc[((size_t)p * BB + b) * DDIM + d];
            float2 mr = st[(size_t)b * LL + 511];
            float v = (__half2float(x[((size_t)b * LL + 511) * DDIM + d]) - mr.x) * mr.y;
            out = w[d] * (v - s * (1.f / 512.f));
        } else if (d < KCAT) {
            out = time_vecs[((size_t)b * LL + 511) * 24 + (d - 512)];
        }
    }
    cath[b * KPADP + d] = __float2half_rn(out);
}

// ---------------------------------------------------------------------------
// Host orchestration
// ---------------------------------------------------------------------------
extern "C" void kernel_launch(void* const* d_in, const int* in_sizes, int n_in,
                              void* d_out, int out_size) {
    (void)in_sizes; (void)n_in; (void)out_size;
    const int*   x_app     = (const int*)  d_in[0];
    const float* x_time    = (const float*)d_in[1];
    const float* time_vecs = (const float*)d_in[2];
    const float* emb       = (const float*)d_in[4];
    const float* time_w    = (const float*)d_in[5];
    const float* time_b    = (const float*)d_in[6];
    const float* Wq        = (const float*)d_in[7];
    const float* bq        = (const float*)d_in[8];
    const float* Wo        = (const float*)d_in[9];
    const float* bo        = (const float*)d_in[10];
    const float* four_wr   = (const float*)d_in[11];
    const float* four_wi   = (const float*)d_in[12];
    const float* conv1     = (const float*)d_in[13];
    const float* conv2     = (const float*)d_in[14];
    const float* norm_w    = (const float*)d_in[15];
    /* norm_b cancels in cat = xh[511] - mean_L(xh) */
    const float* proj_w    = (const float*)d_in[17];
    const float* proj_b    = (const float*)d_in[18];

    float *gacc;
    float2 *gst;
    __half *pa, *pb, *px, *pxt, *yp, *wq, *wo, *c1, *c2, *tw, *itw, *cath, *pwh;
    cudaGetSymbolAddress((void**)&gacc, g_acc);
    cudaGetSymbolAddress((void**)&gst,  g_st);
    cudaGetSymbolAddress((void**)&pa,   g_pa);
    cudaGetSymbolAddress((void**)&pb,   g_pb);
    cudaGetSymbolAddress((void**)&px,   g_px);
    cudaGetSymbolAddress((void**)&pxt,  g_pxt);
    cudaGetSymbolAddress((void**)&yp,   g_yp);
    cudaGetSymbolAddress((void**)&wq,   g_wq);
    cudaGetSymbolAddress((void**)&wo,   g_wo);
    cudaGetSymbolAddress((void**)&c1,   g_c1);
    cudaGetSymbolAddress((void**)&c2,   g_c2);
    cudaGetSymbolAddress((void**)&tw,   g_tw);
    cudaGetSymbolAddress((void**)&itw,  g_itw);
    cudaGetSymbolAddress((void**)&cath, g_cath);
    cudaGetSymbolAddress((void**)&pwh,  g_pwh);

    const int M = MTOT;   // 32768

    init_tw_k<<<128, 256>>>(tw, itw);
    cvt_all_k<<<(NW_TOTAL + 255) / 256, 256>>>(Wq, Wo, conv1, conv2, proj_w,
                                               wq, wo, c1, c2, pwh);
    embed_k<<<dim3(LL, BB), 256>>>(x_app, x_time, emb, time_w, time_b, px);

    dim3 t64grid(8, 8, BB), t64blk(32, 8);
    dim3 mfgrid(2, 16, BB), mtblk(32, 8);   // mtrans_fwd
    dim3 mbgrid(16, 2, BB);                 // mtrans_bwd
    dim3 dgrid(2, 8, BB);

    for (int l = 0; l < 2; l++) {
        const float* bql = bq + (size_t)l * DDIM;
        const float* bol = bo + (size_t)l * DDIM;
        const float* wrl = four_wr + (size_t)l * HH * EE * EE * NMODES;
        const float* wil = four_wi + (size_t)l * HH * EE * EE * NMODES;
        size_t owq = (size_t)l * DDIM * DDIM;
        size_t oc1 = (size_t)l * DFF * DDIM;
        size_t oc2 = (size_t)l * DDIM * DFF;

        // xT = transpose(x): px -> pxt
        transpose64_k<<<t64grid, t64blk>>>(px, pxt);
        // fwd DFT: Xft[(b,d),m] = xT @ TW^T
        mg2<0,0,0,1>(pxt, tw, nullptr, nullptr, nullptr, pa, M, 64, 512, 64, M);
        // Xft -> [(b,m),d]
        mtrans_fwd_k<<<mfgrid, mtblk>>>(pa, pb);
        // q_ft = Xft @ Wq^T  (mode space: M=4096)
        mg2<0,0,0,1>(pb, wq + owq, nullptr, nullptr, nullptr, pa, MMODE, 512, 512, 512, MMODE);
        // complex mode mixing (+512*bq at DC)
        modemix_k<<<dim3(NMODES, HH), 256>>>(pa, bql, wrl, wil, pb);
        // G' = G @ Wo^T  (mode space)
        mg2<0,0,0,1>(pb, wo + owq, nullptr, nullptr, nullptr, pa, MMODE, 512, 512, 512, MMODE);
        // G' -> [(b,d),m], +512*bo at DC
        mtrans_bwd_k<<<mbgrid, mtblk>>>(pa, bol, pb);
        // inv DFT + residual: tmpT[(b,d),l] = G'T @ ITW^T + xT  (K=64)
        mg2<0,1,0,1>(pb, itw, nullptr, pxt, nullptr, pa, M, 512, 64, 512, M);
        // tmpT -> tmp [b,l,d]
        transpose64_k<<<t64grid, t64blk>>>(pa, pb);
        // x = tmp - movavg(tmp)
        decomp_k<<<dgrid, 128>>>(pb, px);
        // y = relu(x @ c1^T)
        mg2<1,0,0,1>(px, c1 + oc1, nullptr, nullptr, nullptr, yp, M, 2048, 512, 2048, M);
        // tmp = y @ c2^T + x
        mg2<0,1,0,1>(yp, c2 + oc2, nullptr, px, nullptr, pb, M, 512, 2048, 512, M);
        // x = tmp - movavg(tmp)
        decomp_k<<<dgrid, 128>>>(pb, px);
    }

    // fused final layernorm (stats-only) + concat
    ln_stats_k<<<dim3(LL, BB), DDIM>>>(px, gst);
    partial_sum_k<<<dim3(8, BB), DDIM>>>(px, gst, gacc);
    lastcat_k<<<128, KPADP>>>(px, gst, gacc, norm_w, time_vecs, cath);
    // score = cat @ proj_w^T + proj_b  (f32 out, Mout=64)
    mg2<0,0,1,0>(cath, pwh, proj_b, nullptr, (float*)d_out, nullptr,
                 128, NPADP, KPADP, NAPP, BB);
}